// round 1
// baseline (speedup 1.0000x reference)
#include <cuda_runtime.h>
#include <cstdint>

// Problem constants (fixed shapes from metadata: x,y float32 (4,4096,6))
#define BB 4
#define NN 4096
#define NPTS (BB*NN)          // 16384 points per set
#define LOG2E 1.4426950408889634f
#define LN2F  0.6931471805599453f
#define EPS2  1e-4f           // BLUR**P
#define BLOG  (-8.317766166719343f)  // -log(4096)

#define POS_INF (__int_as_float(0x7f800000))
#define NEG_INF (__int_as_float(0xff800000))

// -------- device scratch (no dynamic allocation allowed) --------
__device__ __align__(16) float d_U[NPTS*8];     // x points: u0..u5, |u|^2, pad
__device__ __align__(16) float d_V[NPTS*8];     // y points
__device__ __align__(16) float d_Pxy[NPTS*8];   // packed cols for f-softmin: W0..W5, h2, pad
__device__ __align__(16) float d_Pyx[NPTS*8];   // packed cols for g-softmin
__device__ float d_f[2][NPTS];
__device__ float d_g[2][NPTS];
__device__ float d_maxnorm2;
__device__ float d_dmin[6];
__device__ float d_dmax[6];
__device__ float d_s;
__device__ float d_eps1;

// -------- float atomics via ordered-int trick --------
__device__ __forceinline__ void atomicMaxF(float* addr, float v) {
    if (v >= 0.f) atomicMax((int*)addr, __float_as_int(v));
    else          atomicMin((unsigned int*)addr, __float_as_uint(v));
}
__device__ __forceinline__ void atomicMinF(float* addr, float v) {
    if (v >= 0.f) atomicMin((int*)addr, __float_as_int(v));
    else          atomicMax((unsigned int*)addr, __float_as_uint(v));
}

// -------- kernel 0: reset accumulators + zero potentials --------
__global__ void k_init() {
    int idx = blockIdx.x * blockDim.x + threadIdx.x;
    int stride = gridDim.x * blockDim.x;
    for (int i = idx; i < NPTS; i += stride) { d_f[0][i] = 0.f; d_g[0][i] = 0.f; }
    if (blockIdx.x == 0 && threadIdx.x == 0) {
        d_maxnorm2 = 0.f;
        #pragma unroll
        for (int k = 0; k < 6; ++k) { d_dmin[k] = POS_INF; d_dmax[k] = NEG_INF; }
    }
}

// -------- kernel 1: max coord-norm + per-dim min/max over all 32768 points --------
__global__ void k_reduce(const float* __restrict__ x, const float* __restrict__ y) {
    int idx = blockIdx.x * blockDim.x + threadIdx.x;
    int stride = gridDim.x * blockDim.x;
    float mn2 = 0.f;
    float dmn[6], dmx[6];
    #pragma unroll
    for (int k = 0; k < 6; ++k) { dmn[k] = POS_INF; dmx[k] = NEG_INF; }
    for (int p = idx; p < 2*NPTS; p += stride) {
        const float* v = (p < NPTS) ? (x + (size_t)p*6) : (y + (size_t)(p - NPTS)*6);
        float c[6];
        #pragma unroll
        for (int k = 0; k < 6; ++k) c[k] = v[k];
        float n2 = c[0]*c[0] + c[1]*c[1] + c[2]*c[2];
        mn2 = fmaxf(mn2, n2);
        #pragma unroll
        for (int k = 0; k < 6; ++k) { dmn[k] = fminf(dmn[k], c[k]); dmx[k] = fmaxf(dmx[k], c[k]); }
    }
    // warp reduction
    #pragma unroll
    for (int o = 16; o; o >>= 1) {
        mn2 = fmaxf(mn2, __shfl_xor_sync(0xffffffffu, mn2, o));
        #pragma unroll
        for (int k = 0; k < 6; ++k) {
            dmn[k] = fminf(dmn[k], __shfl_xor_sync(0xffffffffu, dmn[k], o));
            dmx[k] = fmaxf(dmx[k], __shfl_xor_sync(0xffffffffu, dmx[k], o));
        }
    }
    __shared__ float s2[8], smn[8][6], smx[8][6];
    int lane = threadIdx.x & 31, w = threadIdx.x >> 5;
    if (lane == 0) {
        s2[w] = mn2;
        #pragma unroll
        for (int k = 0; k < 6; ++k) { smn[w][k] = dmn[k]; smx[w][k] = dmx[k]; }
    }
    __syncthreads();
    if (threadIdx.x == 0) {
        float a2 = s2[0];
        float amn[6], amx[6];
        #pragma unroll
        for (int k = 0; k < 6; ++k) { amn[k] = smn[0][k]; amx[k] = smx[0][k]; }
        for (int wi = 1; wi < 8; ++wi) {
            a2 = fmaxf(a2, s2[wi]);
            #pragma unroll
            for (int k = 0; k < 6; ++k) {
                amn[k] = fminf(amn[k], smn[wi][k]);
                amx[k] = fmaxf(amx[k], smx[wi][k]);
            }
        }
        atomicMaxF(&d_maxnorm2, a2);
        #pragma unroll
        for (int k = 0; k < 6; ++k) { atomicMinF(&d_dmin[k], amn[k]); atomicMaxF(&d_dmax[k], amx[k]); }
    }
}

// -------- kernel 2: scalars --------
__global__ void k_finalize() {
    float e = 0.f;
    #pragma unroll
    for (int k = 0; k < 6; ++k) { float d = d_dmax[k] - d_dmin[k]; e += d * d; }
    d_eps1 = e;                                   // diameter^2 (P=2)
    d_s = 1.f / (sqrtf(d_maxnorm2) + 1e-6f);
}

// -------- kernel 3: build packed point arrays U, V --------
__global__ void k_build(const float* __restrict__ x, const float* __restrict__ y) {
    int p = blockIdx.x * blockDim.x + threadIdx.x;
    if (p >= 2*NPTS) return;
    int q = (p < NPTS) ? p : p - NPTS;
    const float* src = (p < NPTS) ? (x + (size_t)q*6) : (y + (size_t)q*6);
    float* dst = (p < NPTS) ? (d_U + (size_t)q*8) : (d_V + (size_t)q*8);
    float s = d_s;
    float u0 = src[0] * s, u1 = src[1] * s, u2 = src[2] * s;
    float c3 = 0.1f * fminf(fmaxf(src[3], 0.f), 1.f);
    float c4 = 0.1f * fminf(fmaxf(src[4], 0.f), 1.f);
    float c5 = 0.1f * fminf(fmaxf(src[5], 0.f), 1.f);
    float sq = u0*u0 + u1*u1 + u2*u2 + c3*c3 + c4*c4 + c5*c5;
    float4 oa = make_float4(u0, u1, u2, c3);
    float4 ob = make_float4(c4, c5, sq, 0.f);
    reinterpret_cast<float4*>(dst)[0] = oa;
    reinterpret_cast<float4*>(dst)[1] = ob;
}

// -------- kernel 4 (per stage): pack columns W = v*(2*log2e/eps), h2 --------
__global__ void k_pack(int use_eps1, int cur) {
    int p = blockIdx.x * blockDim.x + threadIdx.x;
    if (p >= 2*NPTS) return;
    float eps = use_eps1 ? d_eps1 : EPS2;
    float cW = 2.f * LOG2E / eps;
    float ce = LOG2E / eps;
    int q = (p < NPTS) ? p : p - NPTS;
    const float* src = (p < NPTS) ? (d_V + (size_t)q*8) : (d_U + (size_t)q*8);
    float pot = (p < NPTS) ? d_g[cur][q] : d_f[cur][q];
    float* dst = (p < NPTS) ? (d_Pxy + (size_t)q*8) : (d_Pyx + (size_t)q*8);
    float4 a = reinterpret_cast<const float4*>(src)[0];
    float4 b = reinterpret_cast<const float4*>(src)[1];   // b.z = |v|^2
    float h2 = LOG2E * BLOG + ce * (pot - b.z);
    float4 oa = make_float4(a.x * cW, a.y * cW, a.z * cW, a.w * cW);
    float4 ob = make_float4(b.x * cW, b.y * cW, h2, 0.f);
    reinterpret_cast<float4*>(dst)[0] = oa;
    reinterpret_cast<float4*>(dst)[1] = ob;
}

// -------- kernel 5 (per stage): fused both-direction softmin --------
// grid = (NN/64, 2*BB), block = 256 (8 warps).
// Block handles 64 rows; lane l owns rows (base+l) and (base+32+l); warp w
// covers j in [w*512, (w+1)*512). Per-warp streaming logsumexp partials are
// merged across warps via shared (m, s) pairs.
template<bool USE_EPS1>
__global__ void __launch_bounds__(256) k_main(int cur, float alpha, float beta) {
    const int bd = blockIdx.y;
    const int b = bd & 3;
    const int dir = bd >> 2;
    const float* Rows = (dir ? d_V : d_U) + (size_t)b*NN*8;
    const float* P    = (dir ? d_Pyx : d_Pxy) + (size_t)b*NN*8;
    const float* fin  = (dir ? d_g[cur] : d_f[cur]) + (size_t)b*NN;
    float* fout       = (dir ? d_g[cur^1] : d_f[cur^1]) + (size_t)b*NN;

    const int lane = threadIdx.x & 31;
    const int warp = threadIdx.x >> 5;
    const int rowbase = blockIdx.x * 64;

    const float4 ua = reinterpret_cast<const float4*>(Rows + (size_t)(rowbase+lane)*8)[0];
    const float4 ub = reinterpret_cast<const float4*>(Rows + (size_t)(rowbase+lane)*8)[1];
    const float4 va = reinterpret_cast<const float4*>(Rows + (size_t)(rowbase+32+lane)*8)[0];
    const float4 vb = reinterpret_cast<const float4*>(Rows + (size_t)(rowbase+32+lane)*8)[1];

    float m0 = NEG_INF, m1 = NEG_INF;
    float s0 = 0.f, s1 = 0.f;

    const float4* pj = reinterpret_cast<const float4*>(P) + (size_t)warp * 512 * 2;
    #pragma unroll 4
    for (int j = 0; j < 512; ++j) {
        float4 wa = pj[2*j];
        float4 wb = pj[2*j + 1];
        float A0 = wb.z;
        A0 = fmaf(ua.x, wa.x, A0); A0 = fmaf(ua.y, wa.y, A0);
        A0 = fmaf(ua.z, wa.z, A0); A0 = fmaf(ua.w, wa.w, A0);
        A0 = fmaf(ub.x, wb.x, A0); A0 = fmaf(ub.y, wb.y, A0);
        float A1 = wb.z;
        A1 = fmaf(va.x, wa.x, A1); A1 = fmaf(va.y, wa.y, A1);
        A1 = fmaf(va.z, wa.z, A1); A1 = fmaf(va.w, wa.w, A1);
        A1 = fmaf(vb.x, wb.x, A1); A1 = fmaf(vb.y, wb.y, A1);
        if (USE_EPS1) {
            // eps1 = diameter^2 is large: args are ~ -12 +- 0.1, no max needed.
            s0 += exp2f(A0);
            s1 += exp2f(A1);
        } else {
            // exact streaming logsumexp, single exp per element (branchless)
            float d0 = A0 - m0;
            float e0 = exp2f(-fabsf(d0));
            bool up0 = d0 > 0.f;
            s0 = up0 ? fmaf(s0, e0, 1.f) : (s0 + e0);
            m0 = up0 ? A0 : m0;
            float d1 = A1 - m1;
            float e1 = exp2f(-fabsf(d1));
            bool up1 = d1 > 0.f;
            s1 = up1 ? fmaf(s1, e1, 1.f) : (s1 + e1);
            m1 = up1 ? A1 : m1;
        }
    }
    if (USE_EPS1) { m0 = 0.f; m1 = 0.f; }

    __shared__ float sm[8][64];
    __shared__ float ss[8][64];
    sm[warp][lane] = m0;       ss[warp][lane] = s0;
    sm[warp][lane + 32] = m1;  ss[warp][lane + 32] = s1;
    __syncthreads();

    if (threadIdx.x < 64) {
        int r = threadIdx.x;
        float M = sm[0][r];
        #pragma unroll
        for (int w = 1; w < 8; ++w) M = fmaxf(M, sm[w][r]);
        float S = 0.f;
        #pragma unroll
        for (int w = 0; w < 8; ++w) S += ss[w][r] * exp2f(sm[w][r] - M);
        const float eps = USE_EPS1 ? d_eps1 : EPS2;
        float lse2 = M + log2f(S);
        float squ = Rows[(size_t)(rowbase + r)*8 + 6];
        float val = squ - eps * LN2F * lse2;
        fout[rowbase + r] = alpha * fin[rowbase + r] + beta * val;
    }
}

// -------- kernel 6: final mean reduction --------
__global__ void k_out(float* __restrict__ out) {
    float sum = 0.f;
    for (int i = threadIdx.x; i < NPTS; i += 256)
        sum += d_f[0][i] + d_g[0][i];
    #pragma unroll
    for (int o = 16; o; o >>= 1) sum += __shfl_xor_sync(0xffffffffu, sum, o);
    __shared__ float sw[8];
    int lane = threadIdx.x & 31, w = threadIdx.x >> 5;
    if (lane == 0) sw[w] = sum;
    __syncthreads();
    if (threadIdx.x == 0) {
        float t = 0.f;
        #pragma unroll
        for (int wi = 0; wi < 8; ++wi) t += sw[wi];
        out[0] = t * (10.f / (float)NPTS);
    }
}

extern "C" void kernel_launch(void* const* d_in, const int* in_sizes, int n_in,
                              void* d_out, int out_size) {
    (void)in_sizes; (void)n_in; (void)out_size;
    const float* x = (const float*)d_in[0];
    const float* y = (const float*)d_in[1];
    float* out = (float*)d_out;

    k_init<<<64, 256>>>();
    k_reduce<<<64, 256>>>(x, y);
    k_finalize<<<1, 1>>>();
    k_build<<<(2*NPTS + 255)/256, 256>>>(x, y);

    dim3 g(NN/64, 2*BB);
    // stage 0: f = softmin(eps1, Cxy, b_log); g = softmin(eps1, Cyx, a_log)
    k_pack<<<(2*NPTS + 255)/256, 256>>>(1, 0);
    k_main<true><<<g, 256>>>(0, 0.f, 1.f);
    // stage 1 (eps1): f,g = 0.5*(f + ft), 0.5*(g + gt)
    k_pack<<<(2*NPTS + 255)/256, 256>>>(1, 1);
    k_main<true><<<g, 256>>>(1, 0.5f, 0.5f);
    // stage 2 (eps2)
    k_pack<<<(2*NPTS + 255)/256, 256>>>(0, 0);
    k_main<false><<<g, 256>>>(0, 0.5f, 0.5f);
    // stage 3 (eps2): f_new, g_new
    k_pack<<<(2*NPTS + 255)/256, 256>>>(0, 1);
    k_main<false><<<g, 256>>>(1, 0.f, 1.f);

    k_out<<<1, 256>>>(out);
}